// round 16
// baseline (speedup 1.0000x reference)
#include <cuda_runtime.h>
#include <stdint.h>

// Sampling_26972394619348 — 256-bit (v8.b32) variant of the R6 config.
// w = z_mean[:,None,:] + exp(0.5*z_log_var)[:,None,:] * epsilon   [B,100,3]
// labels_ext = repeat(labels, 100) emitted as float32 values.
//
// Same tiling as the best kernel (1536 float4s = 768 x 32B chunks per
// 256-thread block, 3 front-batched chunks per thread), but every global
// access is one 256-bit ld/st.global.v8.b32 (sm_100+) instead of two
// 128-bit ops. 8-float chunks may straddle one row boundary (300 % 8 != 0);
// handled by a per-chunk split index. Components are (f0+j) % 3 and remain
// valid across the straddle since the row stride 300 === 0 (mod 3).

#define BLOCK   256
#define CVEC    3                   // 256-bit chunks per thread
#define CTILE   (BLOCK * CVEC)      // 768 chunks = 1536 float4s per block
#define NROWS   23                  // rows a block can touch (20.5 + straddle)
#define LVEC    2                   // 256-bit label chunks per thread

__device__ __forceinline__ void ldg256(const void* p, float r[8]) {
    asm volatile("ld.global.nc.v8.b32 {%0,%1,%2,%3,%4,%5,%6,%7}, [%8];"
                 : "=f"(r[0]), "=f"(r[1]), "=f"(r[2]), "=f"(r[3]),
                   "=f"(r[4]), "=f"(r[5]), "=f"(r[6]), "=f"(r[7])
                 : "l"(p));
}
__device__ __forceinline__ void stg256(void* p, const float r[8]) {
    asm volatile("st.global.cs.v8.b32 [%8], {%0,%1,%2,%3,%4,%5,%6,%7};"
                 :: "f"(r[0]), "f"(r[1]), "f"(r[2]), "f"(r[3]),
                    "f"(r[4]), "f"(r[5]), "f"(r[6]), "f"(r[7]), "l"(p)
                 : "memory");
}

__global__ void __launch_bounds__(BLOCK)
sampling_kernel(const float* __restrict__ zm,
                const float* __restrict__ lv,
                const int*   __restrict__ labels,
                const float* __restrict__ eps,
                float* __restrict__ w,
                float* __restrict__ lab,
                unsigned wblocks,   // blocks covering the w region
                unsigned B,
                unsigned nlc)       // label 256-bit chunks = B*100/8
{
    __shared__ float sm_m[NROWS * 3];
    __shared__ float sm_s[NROWS * 3];

    const unsigned t = threadIdx.x;

    if (blockIdx.x < wblocks) {
        const unsigned cbase   = blockIdx.x * CTILE;        // first chunk
        const unsigned rowbase = (cbase * 8u) / 300u;

        if (t < NROWS) {
            unsigned row = rowbase + t;
            if (row < B) {
                sm_m[t*3 + 0] = __ldg(&zm[3u*row + 0]);
                sm_m[t*3 + 1] = __ldg(&zm[3u*row + 1]);
                sm_m[t*3 + 2] = __ldg(&zm[3u*row + 2]);
                sm_s[t*3 + 0] = __expf(0.5f * __ldg(&lv[3u*row + 0]));
                sm_s[t*3 + 1] = __expf(0.5f * __ldg(&lv[3u*row + 1]));
                sm_s[t*3 + 2] = __expf(0.5f * __ldg(&lv[3u*row + 2]));
            }
        }
        __syncthreads();

        // Front-batched 256-bit loads (MLP = 3 x 32B = 96B/thread in flight).
        float e[CVEC][8];
        #pragma unroll
        for (int k = 0; k < CVEC; k++) {
            const unsigned u = cbase + (unsigned)k * BLOCK + t;
            ldg256(&eps[(size_t)u * 8u], e[k]);
        }

        #pragma unroll
        for (int k = 0; k < CVEC; k++) {
            const unsigned u   = cbase + (unsigned)k * BLOCK + t;
            const unsigned f0  = u * 8u;                 // first float index
            const unsigned r0  = f0 / 300u;              // row of lane 0
            const unsigned rem = 300u - (f0 - r0 * 300u);// lanes < rem in r0
            const unsigned lr0 = r0 - rowbase;
            const unsigned lr1 = lr0 + 1u;               // straddle row
            const unsigned ph  = f0 % 3u;                // = (2*(k+t))%3

            float o[8];
            #pragma unroll
            for (int j = 0; j < 8; j++) {
                const unsigned c  = (ph + (unsigned)j) % 3u;
                const unsigned lr = ((unsigned)j < rem) ? lr0 : lr1;
                o[j] = fmaf(sm_s[lr*3 + c], e[k][j], sm_m[lr*3 + c]);
            }
            stg256(&w[(size_t)u * 8u], o);
        }
    } else {
        // Label region: LVEC 256-bit stores per thread (12.5 chunks/row).
        const unsigned q0 = (blockIdx.x - wblocks) * (BLOCK * LVEC) + t;
        #pragma unroll
        for (int k = 0; k < LVEC; k++) {
            const unsigned q = q0 + (unsigned)k * BLOCK;
            if (q < nlc) {
                const unsigned f0  = q * 8u;             // label element index
                const unsigned r0  = f0 / 100u;
                const unsigned rem = 100u - (f0 - r0 * 100u);
                const float l0 = (float)__ldg(&labels[r0]);
                const float l1 = (rem < 8u) ? (float)__ldg(&labels[r0 + 1u]) : l0;
                float o[8];
                #pragma unroll
                for (int j = 0; j < 8; j++)
                    o[j] = ((unsigned)j < rem) ? l0 : l1;
                stg256(&lab[(size_t)f0], o);
            }
        }
    }
}

extern "C" void kernel_launch(void* const* d_in, const int* in_sizes, int n_in,
                              void* d_out, int out_size)
{
    const float* zm     = (const float*)d_in[0];
    const float* lv     = (const float*)d_in[1];
    const int*   labels = (const int*)d_in[2];
    const float* eps    = (const float*)d_in[3];

    const unsigned B   = (unsigned)in_sizes[2];   // labels element count
    const unsigned nwc = B * 300u / 8u;           // w 256-bit chunks
    const unsigned nlc = B * 100u / 8u;           // label 256-bit chunks

    float* w   = (float*)d_out;
    float* lab = (float*)d_out + (size_t)B * 300u;

    const unsigned wblocks = (nwc + CTILE - 1) / CTILE;              // 12800
    const unsigned lblocks = (nlc + BLOCK*LVEC - 1) / (BLOCK*LVEC);  // 6400
    const unsigned grid    = wblocks + lblocks;

    sampling_kernel<<<grid, BLOCK>>>(zm, lv, labels, eps, w, lab,
                                     wblocks, B, nlc);
}